// round 7
// baseline (speedup 1.0000x reference)
#include <cuda_runtime.h>

// HierarchicalPDFSampler — balanced sample-parallel version.
// 1 warp per ray.
// Phase 1 (segment-parallel): cdf scan, segment starts, per-segment
//   (slope, offset, split) published to per-warp shared tables.
// Phase 2 (sample-parallel): each lane handles exactly 4 samples via a
//   branch-free 6-step search over segment starts -> zero divergence.
// Merge is closed-form rank placement (no sort, no atomics).

constexpr int NC   = 64;
constexpr int NOUT = 192;
constexpr int WPB  = 8;
constexpr int STR  = 68;   // padded s_start stride (bank-conflict insurance)
constexpr float INV127 = 1.0f / 127.0f;

__device__ __forceinline__ float uval(int j) {
    return (j >= 127) ? 1.0f : (float)j * INV127;
}

// smallest j in [0,128] with uval(j) >= c
__device__ __forceinline__ int first_ge(float c) {
    int j = (int)ceilf(c * 127.0f);
    j = max(0, min(j, 128));
    while (j > 0   && uval(j - 1) >= c) --j;
    while (j < 128 && uval(j)     <  c) ++j;
    return j;
}

// first j in [jS, jE] with fmaf(uval(j), slope, offv) >= dn   (monotone in j)
__device__ __forceinline__ int split_idx(float slope, float offv, float dn,
                                         int jS, int jE) {
    const float uth = (dn - offv) / slope;     // inf/nan ok -> clamped
    int g = (int)ceilf(uth * 127.0f);
    g = max(jS, min(g, jE));
    while (g > jS && fmaf(uval(g - 1), slope, offv) >= dn) --g;
    while (g < jE && fmaf(uval(g),     slope, offv) <  dn) ++g;
    return g;
}

__global__ __launch_bounds__(WPB * 32)
void hier_pdf_kernel(const float* __restrict__ depth,
                     const float* __restrict__ weights,
                     float* __restrict__ out,
                     int nrays)
{
    __shared__ float  s_merg_all[WPB * NOUT];
    __shared__ float4 s_pack_all[WPB * 64];
    __shared__ int    s_start_all[WPB * STR];

    const int lane = threadIdx.x & 31;
    const int warp = threadIdx.x >> 5;
    const int ray  = blockIdx.x * WPB + warp;
    if (ray >= nrays) return;

    float*  s_merg  = s_merg_all  + warp * NOUT;
    float4* s_pack  = s_pack_all  + warp * 64;
    int*    s_start = s_start_all + warp * STR;

    // ---- coalesced float2 loads ----
    const float2 d2 = ((const float2*)(depth   + (size_t)ray * NC))[lane];
    const float2 w2 = ((const float2*)(weights + (size_t)ray * NC))[lane];

    // ---- bin midpoints ----
    const float dnext  = __shfl_down_sync(0xffffffffu, d2.x, 1);  // depth[2l+2]
    const float b_even = 0.5f * (d2.x + d2.y);                    // bins[2l]
    const float b_odd  = 0.5f * (d2.y + dnext);                   // bins[2l+1]

    // ---- cdf via warp pair-scan of weights[1..62]+1e-5 ----
    const float a0 = (lane == 0)  ? 0.0f : (w2.x + 1e-5f);
    const float a1 = (lane == 31) ? 0.0f : (w2.y + 1e-5f);
    float incl = a0 + a1;
    #pragma unroll
    for (int off = 1; off < 32; off <<= 1) {
        const float t = __shfl_up_sync(0xffffffffu, incl, off);
        if (lane >= off) incl += t;
    }
    const float S      = __shfl_sync(0xffffffffu, incl, 31);
    const float invS   = 1.0f / S;
    const float p_odd  = incl * invS;          // cdf[2l+1]
    const float p_even = (incl - a1) * invS;   // cdf[2l] (lane0: exactly 0)

    // ---- segment start indices + fp-monotonicity repair ----
    int jA = first_ge(p_even);   // start of segment b=2l
    int jB = first_ge(p_odd);    // start of segment b=2l+1
    jB = max(jB, jA);
    int v = jB;
    #pragma unroll
    for (int off = 1; off < 32; off <<= 1) {
        const int t = __shfl_up_sync(0xffffffffu, v, off);
        if (lane >= off) v = max(v, t);
    }
    int pm = __shfl_up_sync(0xffffffffu, v, 1);
    if (lane == 0) pm = 0;
    jA = max(jA, pm);
    jB = max(jB, jA);
    int jC = __shfl_down_sync(0xffffffffu, jA, 1);
    if (lane == 31) jC = 128;

    const float p_next = __shfl_down_sync(0xffffffffu, p_even, 1);  // cdf[2l+2]
    const float b_next = __shfl_down_sync(0xffffffffu, b_even, 1);  // bins[2l+2]

    // ---- segment coefficients ----
    // seg b=2l (lane31: b=62, 'above' clamps -> slope 0, range to 128)
    float ca1, ba1; int jE1;
    if (lane == 31) { ca1 = p_even; ba1 = b_even; jE1 = 128; }
    else            { ca1 = p_odd;  ba1 = b_odd;  jE1 = jB;  }
    const float den1 = ca1 - p_even;
    const float inv1 = (den1 < 1e-5f) ? 1.0f : 1.0f / den1;
    const float slope1 = (ba1 - b_even) * inv1;
    const float off1   = fmaf(-p_even, slope1, b_even);
    const int   sp1    = split_idx(slope1, off1, d2.y, jA, jE1);

    // seg b=2l+1 (lanes 0..30)
    float slope2 = 0.0f, off2 = 0.0f;
    int sp2 = jC;
    if (lane < 31) {
        const float den2 = p_next - p_odd;
        const float inv2 = (den2 < 1e-5f) ? 1.0f : 1.0f / den2;
        slope2 = (b_next - b_odd) * inv2;
        off2   = fmaf(-p_odd, slope2, b_odd);
        sp2    = split_idx(slope2, off2, dnext, jB, jC);
    }

    // ---- publish per-segment tables ----
    s_start[2 * lane] = jA;
    s_pack [2 * lane] = make_float4(slope1, off1, __int_as_float(sp1), 0.0f);
    if (lane < 31) {
        s_start[2 * lane + 1] = jB;
        s_pack [2 * lane + 1] = make_float4(slope2, off2, __int_as_float(sp2), 0.0f);
    } else {
        s_start[63] = 0x7fffffff;   // sentinel: search never selects index 63
    }

    // ---- depth positions: e_i = jSplit(i-1), e_0 = 0 ----
    int e0 = __shfl_up_sync(0xffffffffu, sp2, 1);      // jSplit(2l-1)
    if (lane == 0) e0 = 0;
    s_merg[2 * lane     + e0]  = d2.x;
    s_merg[2 * lane + 1 + sp1] = d2.y;

    __syncwarp();

    // ---- sample-parallel phase: 4 fixed samples per lane ----
    #pragma unroll
    for (int k = 0; k < 4; ++k) {
        const int j = 4 * lane + k;
        // branch-free: largest b in [0,62] with s_start[b] <= j
        int b = 0;
        #pragma unroll
        for (int st = 32; st >= 1; st >>= 1) {
            const int mid = b + st;                 // <= 63
            if (s_start[mid] <= j) b = mid;
        }
        const float4 c = s_pack[b];
        const float  s = fmaf(uval(j), c.x, c.y);
        const int   sp = __float_as_int(c.z);
        const int  pos = j + b + 1 + (j >= sp);
        s_merg[pos] = s;
    }
    __syncwarp();

    // ---- coalesced float4 store: 48 float4 per ray ----
    float4* orow = (float4*)(out + (size_t)ray * NOUT);
    const float4* m4 = (const float4*)s_merg;
    orow[lane] = m4[lane];
    if (lane < 16) orow[32 + lane] = m4[32 + lane];
}

extern "C" void kernel_launch(void* const* d_in, const int* in_sizes, int n_in,
                              void* d_out, int out_size)
{
    const float* depth   = (const float*)d_in[0];  // depth_rays_values_coarse [R,64]
    const float* weights = (const float*)d_in[1];  // coarse_weights           [R,64]
    float* out = (float*)d_out;                    // [R,192]

    const int nrays  = in_sizes[0] / NC;
    const int blocks = (nrays + WPB - 1) / WPB;
    hier_pdf_kernel<<<blocks, WPB * 32>>>(depth, weights, out, nrays);
}

// round 9
// speedup vs baseline: 1.1595x; 1.1595x over previous
#include <cuda_runtime.h>

// HierarchicalPDFSampler — R5 structure, instruction-dieted.
// 1 warp per ray.
//  - inverse-CDF by per-segment direct index ranges (u is linspace)
//  - branch-free ceil-guess + predicated-correction for all boundary indices
//  - fast-path divisions (__fdividef) everywhere
//  - closed-form merge ranks (no sort, no atomics, no search tables)

constexpr int NC   = 64;
constexpr int NOUT = 192;
constexpr int WPB  = 8;
constexpr float INV127 = 1.0f / 127.0f;

__device__ __forceinline__ float uval(int j) {
    return (j >= 127) ? 1.0f : (float)j * INV127;
}

// ~smallest j in [0,128] with uval(j) >= c   (branch-free, 1-step corrections)
__device__ __forceinline__ int start_guess(float c) {
    int g = (int)ceilf(c * 127.0f);          // NaN -> 0 (cvt), then clamped
    g = max(0, min(g, 128));
    g -= (g > 0   && uval(g - 1) >= c) ? 1 : 0;
    g += (g < 128 && uval(g)     <  c) ? 1 : 0;
    return g;
}

// ~first j in [jS, jE] with fmaf(uval(j), slope, offv) >= dn  (branch-free)
__device__ __forceinline__ int split_guess(float slope, float offv, float dn,
                                           int jS, int jE) {
    const float uth = __fdividef(dn - offv, slope);   // inf/nan ok -> clamped
    int g = (int)ceilf(uth * 127.0f);
    g = max(jS, min(g, jE));
    g -= (g > jS && fmaf(uval(g - 1), slope, offv) >= dn) ? 1 : 0;
    g -= (g > jS && fmaf(uval(g - 1), slope, offv) >= dn) ? 1 : 0;
    g += (g < jE && fmaf(uval(g),     slope, offv) <  dn) ? 1 : 0;
    g += (g < jE && fmaf(uval(g),     slope, offv) <  dn) ? 1 : 0;
    return g;
}

__global__ __launch_bounds__(WPB * 32)
void hier_pdf_kernel(const float* __restrict__ depth,
                     const float* __restrict__ weights,
                     float* __restrict__ out,
                     int nrays)
{
    __shared__ float s_merg_all[WPB * NOUT];

    const int lane = threadIdx.x & 31;
    const int warp = threadIdx.x >> 5;
    const int ray  = blockIdx.x * WPB + warp;
    if (ray >= nrays) return;

    float* s_merg = s_merg_all + warp * NOUT;

    // ---- coalesced float2 loads ----
    const float2 d2 = ((const float2*)(depth   + (size_t)ray * NC))[lane];
    const float2 w2 = ((const float2*)(weights + (size_t)ray * NC))[lane];

    // ---- bin midpoints ----
    const float dnext  = __shfl_down_sync(0xffffffffu, d2.x, 1);  // depth[2l+2]
    const float b_even = 0.5f * (d2.x + d2.y);                    // bins[2l]
    const float b_odd  = 0.5f * (d2.y + dnext);                   // bins[2l+1]

    // ---- cdf via warp pair-scan of weights[1..62]+1e-5 ----
    const float a0 = (lane == 0)  ? 0.0f : (w2.x + 1e-5f);
    const float a1 = (lane == 31) ? 0.0f : (w2.y + 1e-5f);
    float incl = a0 + a1;
    #pragma unroll
    for (int off = 1; off < 32; off <<= 1) {
        const float t = __shfl_up_sync(0xffffffffu, incl, off);
        if (lane >= off) incl += t;
    }
    const float S      = __shfl_sync(0xffffffffu, incl, 31);
    const float invS   = __fdividef(1.0f, S);
    const float p_odd  = incl * invS;          // cdf[2l+1]
    const float p_even = (incl - a1) * invS;   // cdf[2l] (lane0: exactly 0)

    // ---- segment start indices + fp-monotonicity repair ----
    int jA = start_guess(p_even);   // start of segment b=2l
    int jB = start_guess(p_odd);    // start of segment b=2l+1
    jB = max(jB, jA);
    int v = jB;
    #pragma unroll
    for (int off = 1; off < 32; off <<= 1) {
        const int t = __shfl_up_sync(0xffffffffu, v, off);
        if (lane >= off) v = max(v, t);
    }
    int pm = __shfl_up_sync(0xffffffffu, v, 1);
    if (lane == 0) pm = 0;
    jA = max(jA, pm);
    jB = max(jB, jA);
    int jC = __shfl_down_sync(0xffffffffu, jA, 1);
    if (lane == 31) jC = 128;

    const float p_next = __shfl_down_sync(0xffffffffu, p_even, 1);  // cdf[2l+2]
    const float b_next = __shfl_down_sync(0xffffffffu, b_even, 1);  // bins[2l+2]

    // ---- segment coefficients ----
    // seg b=2l (lane31: b=62, 'above' clamps -> slope 0, range to 128)
    float ca1, ba1; int jE1;
    if (lane == 31) { ca1 = p_even; ba1 = b_even; jE1 = 128; }
    else            { ca1 = p_odd;  ba1 = b_odd;  jE1 = jB;  }
    const float den1 = ca1 - p_even;
    const float inv1 = (den1 < 1e-5f) ? 1.0f : __fdividef(1.0f, den1);
    const float slope1 = (ba1 - b_even) * inv1;
    const float off1   = fmaf(-p_even, slope1, b_even);
    const int   sp1    = split_guess(slope1, off1, d2.y, jA, jE1);

    // seg b=2l+1 (lanes 0..30)
    float slope2 = 0.0f, off2 = 0.0f;
    int sp2 = jC;
    if (lane < 31) {
        const float den2 = p_next - p_odd;
        const float inv2 = (den2 < 1e-5f) ? 1.0f : __fdividef(1.0f, den2);
        slope2 = (b_next - b_odd) * inv2;
        off2   = fmaf(-p_odd, slope2, b_odd);
        sp2    = split_guess(slope2, off2, dnext, jB, jC);
    }

    // ---- depth positions: e_i = jSplit(i-1), e_0 = 0 ----
    int e0 = __shfl_up_sync(0xffffffffu, sp2, 1);      // jSplit(2l-1)
    if (lane == 0) e0 = 0;
    s_merg[2 * lane     + e0]  = d2.x;
    s_merg[2 * lane + 1 + sp1] = d2.y;

    // ---- unified sample loop over both owned segments ----
    const int jEnd  = (lane == 31) ? 128 : jC;
    const int jBeff = (lane == 31) ? 128 : jB;
    const int base  = 2 * lane + 1;
    #pragma unroll 1
    for (int j = jA; j < jEnd; ++j) {
        const bool second = (j >= jBeff);
        const float sl = second ? slope2 : slope1;
        const float of = second ? off2   : off1;
        const int   sp = second ? sp2    : sp1;
        const float s  = fmaf(uval(j), sl, of);
        const int pos  = j + base + (int)second + (j >= sp ? 1 : 0);
        s_merg[pos] = s;
    }
    __syncwarp();

    // ---- coalesced float4 store: 48 float4 per ray ----
    float4* orow = (float4*)(out + (size_t)ray * NOUT);
    const float4* m4 = (const float4*)s_merg;
    orow[lane] = m4[lane];
    if (lane < 16) orow[32 + lane] = m4[32 + lane];
}

extern "C" void kernel_launch(void* const* d_in, const int* in_sizes, int n_in,
                              void* d_out, int out_size)
{
    const float* depth   = (const float*)d_in[0];  // depth_rays_values_coarse [R,64]
    const float* weights = (const float*)d_in[1];  // coarse_weights           [R,64]
    float* out = (float*)d_out;                    // [R,192]

    const int nrays  = in_sizes[0] / NC;
    const int blocks = (nrays + WPB - 1) / WPB;
    hier_pdf_kernel<<<blocks, WPB * 32>>>(depth, weights, out, nrays);
}

// round 10
// speedup vs baseline: 1.4718x; 1.2694x over previous
#include <cuda_runtime.h>

// HierarchicalPDFSampler — setup-dieted R9 structure.
// 1 warp per ray.
//  - inverse-CDF by per-segment direct index ranges (u is linspace)
//  - start indices: bare ceil-guess (tiling validity enforced by prefix-max)
//  - split indices: fast-div guess + 1+1 predicated corrections
//  - unified position formula pos = j + base + (j>=sp1) + (j>=sp2)
//  - incremental u in the sample loop (no per-iter I2F, no 127-ternary)
//  - closed-form merge ranks (no sort, no atomics, no tables)

constexpr int NC   = 64;
constexpr int NOUT = 192;
constexpr int WPB  = 8;
constexpr float INV127 = 1.0f / 127.0f;

// ~smallest j in [0,128] with j*INV127 >= c (no corrections; ±1 is benign)
__device__ __forceinline__ int start_guess(float c) {
    int g = (int)ceilf(c * 127.0f);
    return max(0, min(g, 128));
}

// ~first j in [jS, jE] with fmaf(j*INV127, slope, offv) >= dn (monotone)
__device__ __forceinline__ int split_guess(float slope, float offv, float dn,
                                           int jS, int jE) {
    const float uth = __fdividef(dn - offv, slope);   // inf/nan ok -> clamped
    int g = (int)ceilf(uth * 127.0f);
    g = max(jS, min(g, jE));
    g -= (g > jS && fmaf((float)(g - 1) * INV127, slope, offv) >= dn) ? 1 : 0;
    g += (g < jE && fmaf((float)g       * INV127, slope, offv) <  dn) ? 1 : 0;
    return g;
}

__global__ __launch_bounds__(WPB * 32)
void hier_pdf_kernel(const float* __restrict__ depth,
                     const float* __restrict__ weights,
                     float* __restrict__ out,
                     int nrays)
{
    __shared__ float s_merg_all[WPB * NOUT];

    const int lane = threadIdx.x & 31;
    const int warp = threadIdx.x >> 5;
    const int ray  = blockIdx.x * WPB + warp;
    if (ray >= nrays) return;

    float* s_merg = s_merg_all + warp * NOUT;

    // ---- coalesced float2 loads ----
    const float2 d2 = ((const float2*)(depth   + (size_t)ray * NC))[lane];
    const float2 w2 = ((const float2*)(weights + (size_t)ray * NC))[lane];

    // ---- bin midpoints ----
    const float dnext  = __shfl_down_sync(0xffffffffu, d2.x, 1);  // depth[2l+2]
    const float b_even = 0.5f * (d2.x + d2.y);                    // bins[2l]
    const float b_odd  = 0.5f * (d2.y + dnext);                   // bins[2l+1]

    // ---- cdf via warp pair-scan of weights[1..62]+1e-5 ----
    const float a0 = (lane == 0)  ? 0.0f : (w2.x + 1e-5f);
    const float a1 = (lane == 31) ? 0.0f : (w2.y + 1e-5f);
    float incl = a0 + a1;
    #pragma unroll
    for (int off = 1; off < 32; off <<= 1) {
        const float t = __shfl_up_sync(0xffffffffu, incl, off);
        if (lane >= off) incl += t;
    }
    const float S      = __shfl_sync(0xffffffffu, incl, 31);
    const float invS   = __fdividef(1.0f, S);
    const float p_odd  = incl * invS;          // cdf[2l+1]
    const float p_even = (incl - a1) * invS;   // cdf[2l] (lane0: exactly 0)

    // ---- segment start indices + tiling repair (prefix-max) ----
    int jA = start_guess(p_even);   // start of segment b=2l
    int jB = start_guess(p_odd);    // start of segment b=2l+1
    jB = max(jB, jA);
    int v = jB;
    #pragma unroll
    for (int off = 1; off < 32; off <<= 1) {
        const int t = __shfl_up_sync(0xffffffffu, v, off);
        if (lane >= off) v = max(v, t);
    }
    int pm = __shfl_up_sync(0xffffffffu, v, 1);
    if (lane == 0) pm = 0;
    jA = max(jA, pm);
    jB = max(jB, jA);
    int jC = __shfl_down_sync(0xffffffffu, jA, 1);
    if (lane == 31) jC = 128;

    const float p_next = __shfl_down_sync(0xffffffffu, p_even, 1);  // cdf[2l+2]
    const float b_next = __shfl_down_sync(0xffffffffu, b_even, 1);  // bins[2l+2]

    // ---- segment coefficients ----
    // seg b=2l (lane31: b=62, 'above' clamps -> slope 0, range to 128)
    float ca1, ba1; int jE1;
    if (lane == 31) { ca1 = p_even; ba1 = b_even; jE1 = 128; }
    else            { ca1 = p_odd;  ba1 = b_odd;  jE1 = jB;  }
    const float den1 = ca1 - p_even;
    const float inv1 = (den1 < 1e-5f) ? 1.0f : __fdividef(1.0f, den1);
    const float slope1 = (ba1 - b_even) * inv1;
    const float off1   = fmaf(-p_even, slope1, b_even);
    const int   sp1    = split_guess(slope1, off1, d2.y, jA, jE1);

    // seg b=2l+1 (lanes 0..30); lane31: sp2 = 128 (never triggers)
    float slope2 = 0.0f, off2 = 0.0f;
    int sp2 = jC;
    if (lane < 31) {
        const float den2 = p_next - p_odd;
        const float inv2 = (den2 < 1e-5f) ? 1.0f : __fdividef(1.0f, den2);
        slope2 = (b_next - b_odd) * inv2;
        off2   = fmaf(-p_odd, slope2, b_odd);
        sp2    = split_guess(slope2, off2, dnext, jB, jC);
    }

    // ---- depth positions: e_i = jSplit(i-1), e_0 = 0 ----
    int e0 = __shfl_up_sync(0xffffffffu, sp2, 1);      // jSplit(2l-1)
    if (lane == 0) e0 = 0;
    s_merg[2 * lane     + e0]  = d2.x;
    s_merg[2 * lane + 1 + sp1] = d2.y;

    // ---- unified sample loop over both owned segments ----
    // pos = j + base + (j>=sp1) + (j>=sp2) reproduces the piecewise formula:
    //   sp1 <= jB so (j>=sp1)=1 for the second segment; sp2 >= jB so
    //   (j>=sp2)=0 for the first.
    const int jEnd  = (lane == 31) ? 128 : jC;
    const int jBeff = (lane == 31) ? 128 : jB;
    const int base  = 2 * lane + 1;
    float u = (float)jA * INV127;
    #pragma unroll 1
    for (int j = jA; j < jEnd; ++j) {
        const bool second = (j >= jBeff);
        const float sl = second ? slope2 : slope1;
        const float of = second ? off2   : off1;
        const float s  = fmaf(u, sl, of);
        int pos = j + base;
        pos += (j >= sp1) ? 1 : 0;
        pos += (j >= sp2) ? 1 : 0;
        s_merg[pos] = s;
        u += INV127;
    }
    __syncwarp();

    // ---- coalesced float4 store: 48 float4 per ray ----
    float4* orow = (float4*)(out + (size_t)ray * NOUT);
    const float4* m4 = (const float4*)s_merg;
    orow[lane] = m4[lane];
    if (lane < 16) orow[32 + lane] = m4[32 + lane];
}

extern "C" void kernel_launch(void* const* d_in, const int* in_sizes, int n_in,
                              void* d_out, int out_size)
{
    const float* depth   = (const float*)d_in[0];  // depth_rays_values_coarse [R,64]
    const float* weights = (const float*)d_in[1];  // coarse_weights           [R,64]
    float* out = (float*)d_out;                    // [R,192]

    const int nrays  = in_sizes[0] / NC;
    const int blocks = (nrays + WPB - 1) / WPB;
    hier_pdf_kernel<<<blocks, WPB * 32>>>(depth, weights, out, nrays);
}